// round 5
// baseline (speedup 1.0000x reference)
#include <cuda_runtime.h>
#include <math.h>

#define KM 16
#define DM 16

typedef unsigned long long u64;

// Staging (written on device by precompute kernel), then copied into constant.
struct Coef {
    u64   M2[KM][DM][DM];   // duplicated (m,m) pairs; zeros above diagonal
    u64   V2[KM][DM];       // duplicated (-v,-v)
    float C[KM];            // Phi / sqrt(2*pi*det)
};
__device__   Coef g_stage;
__constant__ Coef c_coef;

__device__ __forceinline__ u64 fma2(u64 a, u64 b, u64 c) {
    u64 r;
    asm("fma.rn.f32x2 %0, %1, %2, %3;" : "=l"(r) : "l"(a), "l"(b), "l"(c));
    return r;
}
__device__ __forceinline__ u64 pack2(float lo, float hi) {
    u64 r;
    asm("mov.b64 %0, {%1, %2};" : "=l"(r) : "f"(lo), "f"(hi));
    return r;
}
__device__ __forceinline__ void unpack2(u64 v, float& lo, float& hi) {
    asm("mov.b64 {%0, %1}, %2;" : "=f"(lo), "=f"(hi) : "l"(v));
}

// ---------------------------------------------------------------------------
// Precompute: 1 block x 512 threads = 16 warps, one warp per mixture.
// Writes duplicated-pair staging struct directly.
// ---------------------------------------------------------------------------
__global__ void gmm_precompute(const float* __restrict__ Phi,
                               const float* __restrict__ mu,
                               const float* __restrict__ Sigma) {
    __shared__ float L[KM][DM][DM + 1];
    __shared__ float Mi[KM][DM][DM + 1];

    int k    = threadIdx.x >> 5;
    int lane = threadIdx.x & 31;
    int r    = lane & 15;
    bool act = lane < 16;

    if (act)
        for (int j = 0; j < DM; j++)
            L[k][r][j] = Sigma[(k * DM + r) * DM + j];
    __syncwarp();

    for (int p = 0; p < DM; p++) {
        if (act && r == p) {
            float s = L[k][p][p];
            for (int q = 0; q < p; q++) s -= L[k][p][q] * L[k][p][q];
            L[k][p][p] = sqrtf(s);
        }
        __syncwarp();
        if (act && r > p) {
            float s = L[k][r][p];
            for (int q = 0; q < p; q++) s -= L[k][r][q] * L[k][p][q];
            L[k][r][p] = s / L[k][p][p];
        }
        __syncwarp();
    }

    if (act) {
        int c = r;
        for (int i = 0; i < c; i++) Mi[k][i][c] = 0.0f;
        Mi[k][c][c] = 1.0f / L[k][c][c];
        for (int i = c + 1; i < DM; i++) {
            float s = 0.0f;
            for (int q = c; q < i; q++) s += L[k][i][q] * Mi[k][q][c];
            Mi[k][i][c] = -s / L[k][i][i];
        }
    }
    __syncwarp();

    if (act) {
        float v = 0.0f;
        for (int j = 0; j <= r; j++) v += Mi[k][r][j] * mu[k * DM + j];
        g_stage.V2[k][r] = pack2(-v, -v);
        for (int j = 0; j < DM; j++) {
            float m = Mi[k][r][j];
            g_stage.M2[k][r][j] = pack2(m, m);
        }
        if (r == 0) {
            float prod = 1.0f;
            for (int i = 0; i < DM; i++) prod *= L[k][i][i];   // sqrt(det)
            g_stage.C[k] = Phi[k] / (sqrtf(2.0f * 3.14159265358979323846f) * prod);
        }
    }
}

// ---------------------------------------------------------------------------
// Main kernel: 8 samples/thread = 4 packed f32x2 streams; coefficients come
// from __constant__ (uniform port) — zero LSU traffic in the hot loop.
// ---------------------------------------------------------------------------
__device__ __forceinline__ float gmm_scalar_one(const float* __restrict__ samples,
                                                long n) {
    float d[DM];
    for (int j = 0; j < DM; j++) d[j] = samples[n * DM + j];
    float pdf = 0.0f;
    for (int k = 0; k < KM; k++) {
        u64 dv[DM];
        for (int j = 0; j < DM; j++) dv[j] = pack2(d[j], d[j]);
        u64 quad = 0ull;
        for (int i = 0; i < DM; i++) {
            u64 z = c_coef.V2[k][i];
            for (int j = 0; j <= i; j++) z = fma2(c_coef.M2[k][i][j], dv[j], z);
            quad = fma2(z, z, quad);
        }
        float qa, qb;
        unpack2(quad, qa, qb);
        pdf += c_coef.C[k] * __expf(-0.5f * qa);
    }
    return -logf(pdf);
}

#define NP 4   // packed pairs per thread (8 samples)

__global__ __launch_bounds__(256, 1)
void gmm_main(const float4* __restrict__ samples4,
              const float* __restrict__ samples,
              float* __restrict__ out, int N) {
    long t = (long)blockIdx.x * blockDim.x + threadIdx.x;
    long base = t * (2 * NP);
    if (base >= N) return;

    if (base + 2 * NP <= N) {
        u64 d2[NP][DM];
        #pragma unroll
        for (int p = 0; p < NP; p++) {
            float r0[DM], r1[DM];
            #pragma unroll
            for (int q = 0; q < 4; q++) {
                float4 a = samples4[(base + 2 * p) * 4 + q];
                r0[4*q+0] = a.x; r0[4*q+1] = a.y; r0[4*q+2] = a.z; r0[4*q+3] = a.w;
                float4 b = samples4[(base + 2 * p + 1) * 4 + q];
                r1[4*q+0] = b.x; r1[4*q+1] = b.y; r1[4*q+2] = b.z; r1[4*q+3] = b.w;
            }
            #pragma unroll
            for (int j = 0; j < DM; j++) d2[p][j] = pack2(r0[j], r1[j]);
        }

        float pdf[2 * NP];
        #pragma unroll
        for (int s = 0; s < 2 * NP; s++) pdf[s] = 0.0f;

        #pragma unroll 1
        for (int k = 0; k < KM; k++) {
            u64 q2[NP];
            #pragma unroll
            for (int p = 0; p < NP; p++) q2[p] = 0ull;

            #pragma unroll
            for (int i = 0; i < DM; i++) {
                u64 z[NP];
                u64 v0 = c_coef.V2[k][i];
                #pragma unroll
                for (int p = 0; p < NP; p++) z[p] = v0;
                // Row padded to even length; above-diagonal entry is 0, so the
                // extra FMA is a no-op.
                const int rlen = (i & 1) ? (i + 1) : (i + 2);
                #pragma unroll
                for (int j = 0; j < rlen; j += 2) {
                    u64 m0 = c_coef.M2[k][i][j];
                    u64 m1 = c_coef.M2[k][i][j + 1];
                    #pragma unroll
                    for (int p = 0; p < NP; p++) {
                        z[p] = fma2(m0, d2[p][j],     z[p]);
                        z[p] = fma2(m1, d2[p][j + 1], z[p]);
                    }
                }
                #pragma unroll
                for (int p = 0; p < NP; p++) q2[p] = fma2(z[p], z[p], q2[p]);
            }

            float c = c_coef.C[k];
            #pragma unroll
            for (int p = 0; p < NP; p++) {
                float qa, qb;
                unpack2(q2[p], qa, qb);
                pdf[2*p + 0] += c * __expf(-0.5f * qa);
                pdf[2*p + 1] += c * __expf(-0.5f * qb);
            }
        }

        float4 o0, o1;
        o0.x = -__logf(pdf[0]); o0.y = -__logf(pdf[1]);
        o0.z = -__logf(pdf[2]); o0.w = -__logf(pdf[3]);
        o1.x = -__logf(pdf[4]); o1.y = -__logf(pdf[5]);
        o1.z = -__logf(pdf[6]); o1.w = -__logf(pdf[7]);
        *(float4*)&out[base]     = o0;
        *(float4*)&out[base + 4] = o1;
    } else {
        for (long n = base; n < N; n++)
            out[n] = gmm_scalar_one(samples, n);
    }
}

// ---------------------------------------------------------------------------
extern "C" void kernel_launch(void* const* d_in, const int* in_sizes, int n_in,
                              void* d_out, int out_size) {
    const float* samples = (const float*)d_in[0];
    const float* Phi     = (const float*)d_in[1];
    const float* mu      = (const float*)d_in[2];
    const float* Sigma   = (const float*)d_in[3];
    int N = in_sizes[0] / DM;

    gmm_precompute<<<1, 512>>>(Phi, mu, Sigma);

    // Device-to-device async copy of precomputed coefficients into constant
    // memory (graph-capturable; no allocation).
    void* stage_ptr = nullptr;
    cudaGetSymbolAddress(&stage_ptr, g_stage);
    cudaMemcpyToSymbolAsync(c_coef, stage_ptr, sizeof(Coef), 0,
                            cudaMemcpyDeviceToDevice, 0);

    int threads = (N + 2 * NP - 1) / (2 * NP);
    int blocks  = (threads + 255) / 256;
    gmm_main<<<blocks, 256>>>((const float4*)samples, samples, (float*)d_out, N);
}

// round 6
// speedup vs baseline: 1.0229x; 1.0229x over previous
#include <cuda_runtime.h>
#include <math.h>

#define KM 16
#define DM 16

typedef unsigned long long u64;

// Staging (written on device by precompute kernel), then copied into constant.
struct Coef {
    u64   M2[KM][DM][DM];   // duplicated (m,m) pairs; zeros above diagonal
    u64   V2[KM][DM];       // duplicated (-v,-v)
    float C[KM];            // Phi / sqrt(2*pi*det)
};
__device__   Coef g_stage;
__constant__ Coef c_coef;

__device__ __forceinline__ u64 fma2(u64 a, u64 b, u64 c) {
    u64 r;
    asm("fma.rn.f32x2 %0, %1, %2, %3;" : "=l"(r) : "l"(a), "l"(b), "l"(c));
    return r;
}
__device__ __forceinline__ u64 pack2(float lo, float hi) {
    u64 r;
    asm("mov.b64 %0, {%1, %2};" : "=l"(r) : "f"(lo), "f"(hi));
    return r;
}
__device__ __forceinline__ void unpack2(u64 v, float& lo, float& hi) {
    asm("mov.b64 {%0, %1}, %2;" : "=f"(lo), "=f"(hi) : "l"(v));
}

// ---------------------------------------------------------------------------
// Precompute: 1 block x 512 threads = 16 warps, one warp per mixture.
// Writes duplicated-pair staging struct directly.
// ---------------------------------------------------------------------------
__global__ void gmm_precompute(const float* __restrict__ Phi,
                               const float* __restrict__ mu,
                               const float* __restrict__ Sigma) {
    __shared__ float L[KM][DM][DM + 1];
    __shared__ float Mi[KM][DM][DM + 1];

    int k    = threadIdx.x >> 5;
    int lane = threadIdx.x & 31;
    int r    = lane & 15;
    bool act = lane < 16;

    if (act)
        for (int j = 0; j < DM; j++)
            L[k][r][j] = Sigma[(k * DM + r) * DM + j];
    __syncwarp();

    for (int p = 0; p < DM; p++) {
        if (act && r == p) {
            float s = L[k][p][p];
            for (int q = 0; q < p; q++) s -= L[k][p][q] * L[k][p][q];
            L[k][p][p] = sqrtf(s);
        }
        __syncwarp();
        if (act && r > p) {
            float s = L[k][r][p];
            for (int q = 0; q < p; q++) s -= L[k][r][q] * L[k][p][q];
            L[k][r][p] = s / L[k][p][p];
        }
        __syncwarp();
    }

    if (act) {
        int c = r;
        for (int i = 0; i < c; i++) Mi[k][i][c] = 0.0f;
        Mi[k][c][c] = 1.0f / L[k][c][c];
        for (int i = c + 1; i < DM; i++) {
            float s = 0.0f;
            for (int q = c; q < i; q++) s += L[k][i][q] * Mi[k][q][c];
            Mi[k][i][c] = -s / L[k][i][i];
        }
    }
    __syncwarp();

    if (act) {
        float v = 0.0f;
        for (int j = 0; j <= r; j++) v += Mi[k][r][j] * mu[k * DM + j];
        g_stage.V2[k][r] = pack2(-v, -v);
        for (int j = 0; j < DM; j++) {
            float m = Mi[k][r][j];
            g_stage.M2[k][r][j] = pack2(m, m);
        }
        if (r == 0) {
            float prod = 1.0f;
            for (int i = 0; i < DM; i++) prod *= L[k][i][i];   // sqrt(det)
            g_stage.C[k] = Phi[k] / (sqrtf(2.0f * 3.14159265358979323846f) * prod);
        }
    }
}

// ---------------------------------------------------------------------------
// Main kernel: 8 samples/thread = 4 packed f32x2 streams; coefficients come
// from __constant__ (uniform port) — zero LSU traffic in the hot loop.
// ---------------------------------------------------------------------------
__device__ __forceinline__ float gmm_scalar_one(const float* __restrict__ samples,
                                                long n) {
    float d[DM];
    for (int j = 0; j < DM; j++) d[j] = samples[n * DM + j];
    float pdf = 0.0f;
    for (int k = 0; k < KM; k++) {
        u64 dv[DM];
        for (int j = 0; j < DM; j++) dv[j] = pack2(d[j], d[j]);
        u64 quad = 0ull;
        for (int i = 0; i < DM; i++) {
            u64 z = c_coef.V2[k][i];
            for (int j = 0; j <= i; j++) z = fma2(c_coef.M2[k][i][j], dv[j], z);
            quad = fma2(z, z, quad);
        }
        float qa, qb;
        unpack2(quad, qa, qb);
        pdf += c_coef.C[k] * __expf(-0.5f * qa);
    }
    return -logf(pdf);
}

#define NP 4   // packed pairs per thread (8 samples)

__global__ __launch_bounds__(256, 1)
void gmm_main(const float4* __restrict__ samples4,
              const float* __restrict__ samples,
              float* __restrict__ out, int N) {
    long t = (long)blockIdx.x * blockDim.x + threadIdx.x;
    long base = t * (2 * NP);
    if (base >= N) return;

    if (base + 2 * NP <= N) {
        u64 d2[NP][DM];
        #pragma unroll
        for (int p = 0; p < NP; p++) {
            float r0[DM], r1[DM];
            #pragma unroll
            for (int q = 0; q < 4; q++) {
                float4 a = samples4[(base + 2 * p) * 4 + q];
                r0[4*q+0] = a.x; r0[4*q+1] = a.y; r0[4*q+2] = a.z; r0[4*q+3] = a.w;
                float4 b = samples4[(base + 2 * p + 1) * 4 + q];
                r1[4*q+0] = b.x; r1[4*q+1] = b.y; r1[4*q+2] = b.z; r1[4*q+3] = b.w;
            }
            #pragma unroll
            for (int j = 0; j < DM; j++) d2[p][j] = pack2(r0[j], r1[j]);
        }

        float pdf[2 * NP];
        #pragma unroll
        for (int s = 0; s < 2 * NP; s++) pdf[s] = 0.0f;

        #pragma unroll 1
        for (int k = 0; k < KM; k++) {
            u64 q2[NP];
            #pragma unroll
            for (int p = 0; p < NP; p++) q2[p] = 0ull;

            #pragma unroll
            for (int i = 0; i < DM; i++) {
                u64 z[NP];
                u64 v0 = c_coef.V2[k][i];
                #pragma unroll
                for (int p = 0; p < NP; p++) z[p] = v0;
                // Row padded to even length; above-diagonal entry is 0, so the
                // extra FMA is a no-op.
                const int rlen = (i & 1) ? (i + 1) : (i + 2);
                #pragma unroll
                for (int j = 0; j < rlen; j += 2) {
                    u64 m0 = c_coef.M2[k][i][j];
                    u64 m1 = c_coef.M2[k][i][j + 1];
                    #pragma unroll
                    for (int p = 0; p < NP; p++) {
                        z[p] = fma2(m0, d2[p][j],     z[p]);
                        z[p] = fma2(m1, d2[p][j + 1], z[p]);
                    }
                }
                #pragma unroll
                for (int p = 0; p < NP; p++) q2[p] = fma2(z[p], z[p], q2[p]);
            }

            float c = c_coef.C[k];
            #pragma unroll
            for (int p = 0; p < NP; p++) {
                float qa, qb;
                unpack2(q2[p], qa, qb);
                pdf[2*p + 0] += c * __expf(-0.5f * qa);
                pdf[2*p + 1] += c * __expf(-0.5f * qb);
            }
        }

        float4 o0, o1;
        o0.x = -__logf(pdf[0]); o0.y = -__logf(pdf[1]);
        o0.z = -__logf(pdf[2]); o0.w = -__logf(pdf[3]);
        o1.x = -__logf(pdf[4]); o1.y = -__logf(pdf[5]);
        o1.z = -__logf(pdf[6]); o1.w = -__logf(pdf[7]);
        *(float4*)&out[base]     = o0;
        *(float4*)&out[base + 4] = o1;
    } else {
        for (long n = base; n < N; n++)
            out[n] = gmm_scalar_one(samples, n);
    }
}

// ---------------------------------------------------------------------------
extern "C" void kernel_launch(void* const* d_in, const int* in_sizes, int n_in,
                              void* d_out, int out_size) {
    const float* samples = (const float*)d_in[0];
    const float* Phi     = (const float*)d_in[1];
    const float* mu      = (const float*)d_in[2];
    const float* Sigma   = (const float*)d_in[3];
    int N = in_sizes[0] / DM;

    gmm_precompute<<<1, 512>>>(Phi, mu, Sigma);

    // Device-to-device async copy of precomputed coefficients into constant
    // memory (graph-capturable; no allocation).
    void* stage_ptr = nullptr;
    cudaGetSymbolAddress(&stage_ptr, g_stage);
    cudaMemcpyToSymbolAsync(c_coef, stage_ptr, sizeof(Coef), 0,
                            cudaMemcpyDeviceToDevice, 0);

    int threads = (N + 2 * NP - 1) / (2 * NP);
    int blocks  = (threads + 255) / 256;
    gmm_main<<<blocks, 256>>>((const float4*)samples, samples, (float*)d_out, N);
}

// round 9
// speedup vs baseline: 1.5672x; 1.5322x over previous
#include <cuda_runtime.h>
#include <math.h>

#define KM 16
#define DM 16
#define SPT 14          // samples per thread: one NP=4 batch + one NP=3 batch

typedef unsigned int u32;
typedef unsigned long long u64;

__device__ __forceinline__ u64 fma2(u64 a, u64 b, u64 c) {
    u64 r;
    asm("fma.rn.f32x2 %0, %1, %2, %3;" : "=l"(r) : "l"(a), "l"(b), "l"(c));
    return r;
}
__device__ __forceinline__ u64 pack2(float lo, float hi) {
    u64 r;
    asm("mov.b64 %0, {%1, %2};" : "=l"(r) : "f"(lo), "f"(hi));
    return r;
}
__device__ __forceinline__ void unpack2(u64 v, float& lo, float& hi) {
    asm("mov.b64 {%0, %1}, %2;" : "=f"(lo), "=f"(hi) : "l"(v));
}

// Shared-memory union: precompute scratch overlays the packed main tables.
union __align__(16) SU {
    struct {
        float L [KM][DM][DM + 1];
        float Mi[KM][DM][DM + 1];
    } pre;                                  // 34816 B
    struct {
        u64 M2[KM][DM][DM];                 // duplicated (m,m); zeros above diag
        u64 V2[KM][DM];                     // duplicated (-v,-v)
    } mc;                                   // 34816 B
};

// ---------------------------------------------------------------------------
// Packed-pair batch: 2*NP samples through the k-loop.
// out stores use float2 only: base is always 8B-aligned (even), never 16B.
// ---------------------------------------------------------------------------
template <int NP>
__device__ __forceinline__ void process_batch(const float4* __restrict__ samples4,
                                              float* __restrict__ out,
                                              long base, const SU& su,
                                              const float* sC) {
    u64 d2[NP][DM];
    #pragma unroll
    for (int p = 0; p < NP; p++) {
        float r0[DM], r1[DM];
        #pragma unroll
        for (int q = 0; q < 4; q++) {
            float4 a = samples4[(base + 2 * p) * 4 + q];
            r0[4*q+0] = a.x; r0[4*q+1] = a.y; r0[4*q+2] = a.z; r0[4*q+3] = a.w;
            float4 b = samples4[(base + 2 * p + 1) * 4 + q];
            r1[4*q+0] = b.x; r1[4*q+1] = b.y; r1[4*q+2] = b.z; r1[4*q+3] = b.w;
        }
        #pragma unroll
        for (int j = 0; j < DM; j++) d2[p][j] = pack2(r0[j], r1[j]);
    }

    float pdf[2 * NP];
    #pragma unroll
    for (int s = 0; s < 2 * NP; s++) pdf[s] = 0.0f;

    #pragma unroll 1
    for (int k = 0; k < KM; k++) {
        u64 q2[NP];
        #pragma unroll
        for (int p = 0; p < NP; p++) q2[p] = 0ull;

        #pragma unroll
        for (int i = 0; i < DM; i++) {
            u64 z[NP];
            u64 v0 = su.mc.V2[k][i];
            #pragma unroll
            for (int p = 0; p < NP; p++) z[p] = v0;
            // Row padded to even length; above-diagonal entry is 0 (no-op FMA).
            const int rlen = (i & 1) ? (i + 1) : (i + 2);
            #pragma unroll
            for (int j = 0; j < rlen; j += 2) {
                ulonglong2 m2 = *(const ulonglong2*)&su.mc.M2[k][i][j];
                #pragma unroll
                for (int p = 0; p < NP; p++) {
                    z[p] = fma2(m2.x, d2[p][j],     z[p]);
                    z[p] = fma2(m2.y, d2[p][j + 1], z[p]);
                }
            }
            #pragma unroll
            for (int p = 0; p < NP; p++) q2[p] = fma2(z[p], z[p], q2[p]);
        }

        float c = sC[k];
        #pragma unroll
        for (int p = 0; p < NP; p++) {
            float qa, qb;
            unpack2(q2[p], qa, qb);
            pdf[2*p + 0] += c * __expf(-0.5f * qa);
            pdf[2*p + 1] += c * __expf(-0.5f * qb);
        }
    }

    #pragma unroll
    for (int p = 0; p < NP; p++) {
        float2 o;
        o.x = -__logf(pdf[2*p + 0]);
        o.y = -__logf(pdf[2*p + 1]);
        *(float2*)&out[base + 2 * p] = o;
    }
}

// ---------------------------------------------------------------------------
// Fused kernel: per-block coefficient prologue + balanced 14-sample batches.
// ---------------------------------------------------------------------------
__global__ __launch_bounds__(256, 1)
void gmm_fused(const float4* __restrict__ samples4,
               const float* __restrict__ samples,
               const float* __restrict__ Phi,
               const float* __restrict__ mu,
               const float* __restrict__ Sigma,
               float* __restrict__ out, int N) {
    __shared__ SU su;
    __shared__ float sC[KM];

    const int tid  = threadIdx.x;
    const int wid  = tid >> 5;
    const int lane = tid & 31;
    const int k    = wid * 2 + (lane >> 4);   // 8 warps x 2 mixtures
    const int r    = lane & 15;

    // ---- Prologue: Cholesky + triangular inverse, 2 mixtures per warp ----
    for (int j = 0; j < DM; j++)
        su.pre.L[k][r][j] = Sigma[(k * DM + r) * DM + j];
    __syncwarp();

    for (int p = 0; p < DM; p++) {
        if (r == p) {
            float s = su.pre.L[k][p][p];
            for (int q = 0; q < p; q++) s -= su.pre.L[k][p][q] * su.pre.L[k][p][q];
            su.pre.L[k][p][p] = sqrtf(s);
        }
        __syncwarp();
        if (r > p) {
            float s = su.pre.L[k][r][p];
            for (int q = 0; q < p; q++) s -= su.pre.L[k][r][q] * su.pre.L[k][p][q];
            su.pre.L[k][r][p] = s / su.pre.L[k][p][p];
        }
        __syncwarp();
    }

    // Mi = L^{-1}: lane r computes column r.
    {
        int c = r;
        for (int i = 0; i < c; i++) su.pre.Mi[k][i][c] = 0.0f;
        su.pre.Mi[k][c][c] = 1.0f / su.pre.L[k][c][c];
        for (int i = c + 1; i < DM; i++) {
            float s = 0.0f;
            for (int q = c; q < i; q++) s += su.pre.L[k][i][q] * su.pre.Mi[k][q][c];
            su.pre.Mi[k][i][c] = -s / su.pre.L[k][i][i];
        }
    }
    __syncwarp();

    // Pull row r of Mi into registers; compute v_r; lane 0 computes the norm.
    float mrow[DM];
    for (int j = 0; j < DM; j++)
        mrow[j] = (j <= r) ? su.pre.Mi[k][r][j] : 0.0f;
    float v = 0.0f;
    for (int j = 0; j <= r; j++) v += mrow[j] * mu[k * DM + j];
    if (r == 0) {
        float prodL = 1.0f;
        for (int i = 0; i < DM; i++) prodL *= su.pre.L[k][i][i];   // sqrt(det)
        sC[k] = Phi[k] / (sqrtf(2.0f * 3.14159265358979323846f) * prodL);
    }
    __syncthreads();

    // Transcribe into packed main tables (overlays the prologue scratch).
    for (int j = 0; j < DM; j++)
        su.mc.M2[k][r][j] = pack2(mrow[j], mrow[j]);
    su.mc.V2[k][r] = pack2(-v, -v);
    __syncthreads();

    // ---- Main: 14 samples per thread = NP4 + NP3 ----
    long t = (long)blockIdx.x * blockDim.x + tid;
    long base = t * SPT;
    if (base >= N) return;

    if (base + SPT <= N) {
        process_batch<4>(samples4, out, base,     su, sC);
        process_batch<3>(samples4, out, base + 8, su, sC);
    } else {
        for (long n = base; n < N; n++) {
            float d[DM];
            for (int j = 0; j < DM; j++) d[j] = samples[n * DM + j];
            float pdf = 0.0f;
            for (int kk = 0; kk < KM; kk++) {
                float quad = 0.0f;
                for (int i = 0; i < DM; i++) {
                    float z = -((const float*)&su.mc.V2[kk][i])[0];
                    for (int j = 0; j <= i; j++)
                        z = fmaf(((const float*)&su.mc.M2[kk][i][j])[0], d[j], z);
                    quad = fmaf(z, z, quad);
                }
                pdf += sC[kk] * __expf(-0.5f * quad);
            }
            out[n] = -logf(pdf);
        }
    }
}

// ---------------------------------------------------------------------------
extern "C" void kernel_launch(void* const* d_in, const int* in_sizes, int n_in,
                              void* d_out, int out_size) {
    const float* samples = (const float*)d_in[0];
    const float* Phi     = (const float*)d_in[1];
    const float* mu      = (const float*)d_in[2];
    const float* Sigma   = (const float*)d_in[3];
    int N = in_sizes[0] / DM;

    long threads = ((long)N + SPT - 1) / SPT;
    int  blocks  = (int)((threads + 255) / 256);
    gmm_fused<<<blocks, 256>>>((const float4*)samples, samples,
                               Phi, mu, Sigma, (float*)d_out, N);
}